// round 7
// baseline (speedup 1.0000x reference)
#include <cuda_runtime.h>
#include <cstdint>

// ---------------------------------------------------------------------------
// GraphConv: out[node] = relu(sum(self+neighbors) @ W[deg(node)] + b[deg(node)])
// Counting-sort nodes by degree, then per-128-row-tile tf32 mma.sync GEMM with
// fused neighbor gather (A tile built in SMEM) and fused bias+relu epilogue.
// NOTE: build targets plain sm_103 (no 'a' suffix) -> tcgen05/TMA unavailable;
// Ampere-class mma.sync (HMMA) is the fastest compilable tensor path.
// R6 fix: mma A-fragment register order (a1 = row+8, a2 = col+4; were swapped).
// ---------------------------------------------------------------------------

#define NB      256
#define NNLOC   512
#define NNODES  (NB * NNLOC)      // 131072
#define DSLOTS  6
#define FIN     128
#define FOUT    128
#define NDEG    6
#define MAXTILES 1030             // ceil-sum bound is 1029

// ------------------------- device scratch (no allocs) ----------------------
__device__ int           g_nbr[NNODES * DSLOTS];
__device__ unsigned char g_deg[NNODES];
__device__ int           g_perm[NNODES];
__device__ int           g_hist[8];
__device__ int           g_cnt[8];
__device__ int           g_grpbase[8];
__device__ int           g_tilebase[8];
__device__ int           g_totaltiles;
__device__ int           g_is64;
__device__ float         g_Wt[NDEG * FIN * FOUT];   // W[d] transposed to [n][k], tf32-rounded

// ------------------------- helpers ------------------------------------------
__device__ __forceinline__ float to_tf32(float x) {
    uint32_t u = __float_as_uint(x), o;
    asm("cvt.rna.tf32.f32 %0, %1;" : "=r"(o) : "r"(u));
    return __uint_as_float(o);
}

// ------------------------- kernel 1: W transpose + init --------------------
__global__ void k_prep(const float* __restrict__ W, const void* __restrict__ edges) {
    int idx = blockIdx.x * 256 + threadIdx.x;
    if (blockIdx.x == 0 && threadIdx.x == 0) {
        // sniff edges dtype: int64 -> every odd 32-bit word is 0 or -1
        const int* e32 = (const int*)edges;
        int is64 = 1;
        for (int i = 0; i < 128; i++) {
            int hi = e32[2 * i + 1];
            if (hi != 0 && hi != -1) { is64 = 0; break; }
        }
        g_is64 = is64;
    }
    if (blockIdx.x == 0 && threadIdx.x < 8) g_hist[threadIdx.x] = 0;
    if (idx < NDEG * FIN * FOUT) {
        int d = idx >> 14;            // / 16384
        int r = idx & 16383;
        int n = r >> 7;
        int k = r & 127;
        g_Wt[idx] = to_tf32(W[d * 16384 + k * 128 + n]);  // Wt[d][n][k]
    }
}

// ------------------------- kernel 2: degrees + histogram --------------------
__global__ void k_deg(const void* __restrict__ edges) {
    __shared__ int sh[6];
    int tid = threadIdx.x;
    if (tid < 6) sh[tid] = 0;
    __syncthreads();
    int g = blockIdx.x * 256 + tid;
    int deg = 0;
    int nb[6];
    if (g_is64) {
        const long long* e = (const long long*)edges + (size_t)g * 6;
        #pragma unroll
        for (int j = 0; j < 6; j++) { long long v = e[j]; nb[j] = (int)v; deg += (v >= 0); }
    } else {
        const int* e = (const int*)edges + (size_t)g * 6;
        #pragma unroll
        for (int j = 0; j < 6; j++) { int v = e[j]; nb[j] = v; deg += (v >= 0); }
    }
    #pragma unroll
    for (int j = 0; j < 6; j++) g_nbr[g * 6 + j] = nb[j];
    g_deg[g] = (unsigned char)deg;
    atomicAdd(&sh[deg], 1);
    __syncthreads();
    if (tid < 6) atomicAdd(&g_hist[tid], sh[tid]);
}

// ------------------------- kernel 3: prefix ---------------------------------
__global__ void k_prefix() {
    int b = 0, tb = 0;
    for (int d = 0; d < NDEG; d++) {
        g_grpbase[d]  = b;
        g_tilebase[d] = tb;
        b  += g_hist[d];
        tb += (g_hist[d] + 127) >> 7;
        g_cnt[d] = 0;
    }
    g_tilebase[NDEG] = tb;
    g_totaltiles = tb;
}

// ------------------------- kernel 4: build permutation ----------------------
__global__ void k_perm() {
    __shared__ int s_loc[6], s_base[6];
    int tid = threadIdx.x;
    if (tid < 6) s_loc[tid] = 0;
    __syncthreads();
    int g = blockIdx.x * 256 + tid;
    int d = g_deg[g];
    int l = atomicAdd(&s_loc[d], 1);
    __syncthreads();
    if (tid < 6) s_base[tid] = atomicAdd(&g_cnt[tid], s_loc[tid]);
    __syncthreads();
    g_perm[g_grpbase[d] + s_base[d] + l] = g;
}

// ------------------------- kernel 5: fused gather + tf32 mma GEMM -----------
#define LDT 132  // padded row stride (floats): conflict-free fragment loads

static constexpr unsigned OFF_NODE = 0;                  // 128 ints
static constexpr unsigned OFF_BIAS = 512;                // 128 floats
static constexpr unsigned OFF_A    = 1024;               // 128*132*4 = 67584
static constexpr unsigned OFF_W    = 1024 + 128 * LDT * 4;
static constexpr unsigned SMEM_TOTAL = OFF_W + 128 * LDT * 4;  // 136192 B

__global__ void __launch_bounds__(256, 1)
k_gemm(const float* __restrict__ atoms, const float* __restrict__ bias,
       float* __restrict__ out) {
    extern __shared__ __align__(16) unsigned char smem[];
    int tid = threadIdx.x, wid = tid >> 5, lane = tid & 31;
    int t = blockIdx.x;
    if (t >= g_totaltiles) return;   // uniform per CTA

    int d = 0;
    #pragma unroll
    for (int i = 0; i < NDEG - 1; i++)
        if (t >= g_tilebase[i + 1]) d = i + 1;
    int m0     = (t - g_tilebase[d]) << 7;
    int gstart = g_grpbase[d];
    int gcount = g_hist[d];

    int*   sm_node = (int*)(smem + OFF_NODE);
    float* sm_bias = (float*)(smem + OFF_BIAS);
    float* As      = (float*)(smem + OFF_A);   // [128][LDT]
    float* Ws      = (float*)(smem + OFF_W);   // [128][LDT]  (Wt[n][k])
    if (tid < 128) sm_bias[tid] = bias[d * 128 + tid];

    // --- W[d] tile: contiguous [n][k] tf32, copy into padded smem ---
    {
        const float4* Wt4 = (const float4*)(g_Wt + d * 16384);
        for (int idx = tid; idx < 4096; idx += 256) {
            int row = idx >> 5, k4 = idx & 31;
            *(float4*)&Ws[row * LDT + k4 * 4] = Wt4[idx];
        }
    }

    // --- A tile: gather self + neighbors, sum, rna-round ---
    for (int row = wid; row < 128; row += 8) {
        int slot = m0 + row;
        int node = (slot < gcount) ? g_perm[gstart + slot] : -1;
        if (lane == 0) sm_node[row] = node;
        float4 acc = make_float4(0.f, 0.f, 0.f, 0.f);
        if (node >= 0) {
            const float4* self = (const float4*)(atoms + ((size_t)node << 7));
            acc = self[lane];
            int bb = node & ~(NNLOC - 1);
            const int2* nb2 = (const int2*)(g_nbr + node * 6);
            int2 e0 = nb2[0], e1 = nb2[1], e2 = nb2[2];
            int ns[6] = {e0.x, e0.y, e1.x, e1.y, e2.x, e2.y};
            #pragma unroll
            for (int j = 0; j < 6; j++) {
                int n = ns[j];
                if (n >= 0) {
                    float4 v = ((const float4*)(atoms + ((size_t)(bb + n) << 7)))[lane];
                    acc.x += v.x; acc.y += v.y; acc.z += v.z; acc.w += v.w;
                }
            }
        }
        acc.x = to_tf32(acc.x); acc.y = to_tf32(acc.y);
        acc.z = to_tf32(acc.z); acc.w = to_tf32(acc.w);
        *(float4*)&As[row * LDT + lane * 4] = acc;
    }
    __syncthreads();

    // --- mma.sync tf32: warp grid 4(M) x 2(N), each warp 32x64 ---
    int warp_m = wid & 3, warp_n = wid >> 2;
    int mb = warp_m * 32, nbase = warp_n * 64;
    int la = lane & 3, lg = lane >> 2;

    float acc[2][8][4];
    #pragma unroll
    for (int mt = 0; mt < 2; mt++)
        #pragma unroll
        for (int nt = 0; nt < 8; nt++)
            #pragma unroll
            for (int q = 0; q < 4; q++) acc[mt][nt][q] = 0.f;

    const uint32_t* Au = (const uint32_t*)As;
    const uint32_t* Wu = (const uint32_t*)Ws;

    #pragma unroll
    for (int kk = 0; kk < 16; kk++) {
        int k0 = kk * 8;
        uint32_t a[2][4];
        #pragma unroll
        for (int mt = 0; mt < 2; mt++) {
            int r = mb + mt * 16 + lg;
            // PTX m16n8k8 tf32 A fragment: a0=(r,c) a1=(r+8,c) a2=(r,c+4) a3=(r+8,c+4)
            a[mt][0] = Au[r * LDT + k0 + la];
            a[mt][1] = Au[(r + 8) * LDT + k0 + la];
            a[mt][2] = Au[r * LDT + k0 + la + 4];
            a[mt][3] = Au[(r + 8) * LDT + k0 + la + 4];
        }
        uint32_t b[8][2];
        #pragma unroll
        for (int nt = 0; nt < 8; nt++) {
            int n = nbase + nt * 8 + lg;
            // B fragment (.col): b0=(k=la, n) b1=(k=la+4, n)
            b[nt][0] = Wu[n * LDT + k0 + la];
            b[nt][1] = Wu[n * LDT + k0 + la + 4];
        }
        #pragma unroll
        for (int mt = 0; mt < 2; mt++)
            #pragma unroll
            for (int nt = 0; nt < 8; nt++)
                asm volatile(
                    "mma.sync.aligned.m16n8k8.row.col.f32.tf32.tf32.f32 "
                    "{%0,%1,%2,%3}, {%4,%5,%6,%7}, {%8,%9}, {%0,%1,%2,%3};"
                    : "+f"(acc[mt][nt][0]), "+f"(acc[mt][nt][1]),
                      "+f"(acc[mt][nt][2]), "+f"(acc[mt][nt][3])
                    : "r"(a[mt][0]), "r"(a[mt][1]), "r"(a[mt][2]), "r"(a[mt][3]),
                      "r"(b[nt][0]), "r"(b[nt][1]));
    }
    __syncthreads();   // everyone done reading As before we overwrite it with C

    // --- stage C in smem (reuse A region) for coalesced output ---
    #pragma unroll
    for (int mt = 0; mt < 2; mt++) {
        int r = mb + mt * 16 + lg;
        #pragma unroll
        for (int nt = 0; nt < 8; nt++) {
            int c = nbase + nt * 8 + la * 2;
            *(float2*)&As[r * LDT + c]       = make_float2(acc[mt][nt][0], acc[mt][nt][1]);
            *(float2*)&As[(r + 8) * LDT + c] = make_float2(acc[mt][nt][2], acc[mt][nt][3]);
        }
    }
    __syncthreads();

    // --- bias + relu + coalesced scatter: warp w owns rows [16w, 16w+16) ---
    float4 bv = *(float4*)&sm_bias[lane * 4];
    #pragma unroll
    for (int i = 0; i < 16; i++) {
        int r = wid * 16 + i;
        int node = sm_node[r];
        if (node >= 0) {
            float4 v = *(float4*)&As[r * LDT + lane * 4];
            v.x = fmaxf(v.x + bv.x, 0.f);
            v.y = fmaxf(v.y + bv.y, 0.f);
            v.z = fmaxf(v.z + bv.z, 0.f);
            v.w = fmaxf(v.w + bv.w, 0.f);
            *(float4*)(out + ((size_t)node << 7) + lane * 4) = v;
        }
    }
}

// ------------------------- launch -------------------------------------------
extern "C" void kernel_launch(void* const* d_in, const int* in_sizes, int n_in,
                              void* d_out, int out_size) {
    const float* atoms = (const float*)d_in[0];
    const void*  edges = d_in[1];
    const float* W     = (const float*)d_in[2];
    const float* b     = (const float*)d_in[3];
    float* out = (float*)d_out;
    (void)in_sizes; (void)n_in; (void)out_size;

    cudaFuncSetAttribute(k_gemm, cudaFuncAttributeMaxDynamicSharedMemorySize, SMEM_TOTAL);

    k_prep<<<(NDEG * FIN * FOUT + 255) / 256, 256>>>(W, edges);
    k_deg<<<NNODES / 256, 256>>>(edges);
    k_prefix<<<1, 1>>>();
    k_perm<<<NNODES / 256, 256>>>();
    k_gemm<<<MAXTILES, 256, SMEM_TOTAL>>>(atoms, b, out);
}

// round 8
// speedup vs baseline: 1.8321x; 1.8321x over previous
#include <cuda_runtime.h>
#include <cstdint>

// ---------------------------------------------------------------------------
// GraphConv: out[node] = relu(sum(self+neighbors) @ W[deg(node)] + b[deg(node)])
// Counting-sort nodes by degree, then per-128-row-tile tf32 mma.sync GEMM with
// fused high-MLP neighbor gather (A tile in SMEM) and fused bias+relu epilogue.
// R8: two-phase gather (indices staged, 2-row unroll), W read as B-fragments
// straight from global (no W smem tile), 2 CTAs/SM, prep kernels fused.
// NOTE: build targets plain sm_103 -> tcgen05/TMA unavailable; mma.sync it is.
// ---------------------------------------------------------------------------

#define NB      256
#define NNLOC   512
#define NNODES  (NB * NNLOC)      // 131072
#define DSLOTS  6
#define FIN     128
#define FOUT    128
#define NDEG    6
#define MAXTILES 1030             // ceil-sum bound is 1029

// ------------------------- device scratch (no allocs) ----------------------
__device__ int           g_nbr[NNODES * DSLOTS];
__device__ unsigned char g_deg[NNODES];
__device__ int           g_perm[NNODES];
__device__ int           g_hist[8];          // zero at load; k_prefix re-zeros
__device__ int           g_cnt[8];
__device__ int           g_grpbase[8];
__device__ int           g_tilebase[8];
__device__ int           g_totaltiles;
// W in B-fragment order: g_Wf[d][kk][n][la] = float2( Wt[n][kk*8+la], Wt[n][kk*8+la+4] )
// where Wt[n][k] = tf32(W[d][k][n]).  float2 index = ((d*16+kk)*128 + n)*4 + la
__device__ float2        g_Wf[NDEG * 16 * 128 * 4];

// ------------------------- helpers ------------------------------------------
__device__ __forceinline__ float to_tf32(float x) {
    uint32_t u = __float_as_uint(x), o;
    asm("cvt.rna.tf32.f32 %0, %1;" : "=r"(o) : "r"(u));
    return __uint_as_float(o);
}

// ------------------------- kernel 1: deg/hist + W fragment prep -------------
__global__ void k_prep_deg(const float* __restrict__ W, const void* __restrict__ edges) {
    __shared__ int sh[6];
    __shared__ int s_is64;
    int tid = threadIdx.x;
    if (tid < 6) sh[tid] = 0;
    if (tid == 0) {
        // sniff edges dtype: int64 -> every odd 32-bit word is 0 or -1
        const int* e32 = (const int*)edges;
        int is64 = 1;
        #pragma unroll 8
        for (int i = 0; i < 128; i++) {
            int hi = e32[2 * i + 1];
            if (hi != 0 && hi != -1) { is64 = 0; break; }
        }
        s_is64 = is64;
    }
    __syncthreads();

    // --- degree + neighbor extraction for node g ---
    int g = blockIdx.x * 256 + tid;
    int deg = 0;
    int nb[6];
    if (s_is64) {
        const long long* e = (const long long*)edges + (size_t)g * 6;
        #pragma unroll
        for (int j = 0; j < 6; j++) { long long v = e[j]; nb[j] = (int)v; deg += (v >= 0); }
    } else {
        const int* e = (const int*)edges + (size_t)g * 6;
        #pragma unroll
        for (int j = 0; j < 6; j++) { int v = e[j]; nb[j] = v; deg += (v >= 0); }
    }
    #pragma unroll
    for (int j = 0; j < 6; j++) g_nbr[g * 6 + j] = nb[j];
    g_deg[g] = (unsigned char)deg;
    atomicAdd(&sh[deg], 1);
    __syncthreads();
    if (tid < 6) atomicAdd(&g_hist[tid], sh[tid]);

    // --- W fragment prep: 49152 float2, blocks 0..191 ---
    int fid = blockIdx.x * 256 + tid;
    if (fid < NDEG * 16 * 128 * 4) {
        int d  = fid >> 13;            // / 8192
        int r  = fid & 8191;
        int kk = r >> 9;               // / 512
        int r2 = r & 511;
        int n  = r2 >> 2;
        int la = r2 & 3;
        int k0 = kk * 8;
        float lo = to_tf32(W[(d * 128 + (k0 + la)) * 128 + n]);
        float hi = to_tf32(W[(d * 128 + (k0 + la + 4)) * 128 + n]);
        g_Wf[fid] = make_float2(lo, hi);
    }
}

// ------------------------- kernel 2: prefix (self-cleaning) -----------------
__global__ void k_prefix() {
    int b = 0, tb = 0;
    for (int d = 0; d < NDEG; d++) {
        g_grpbase[d]  = b;
        g_tilebase[d] = tb;
        b  += g_hist[d];
        tb += (g_hist[d] + 127) >> 7;
        g_cnt[d]  = 0;
        g_hist[d] = 0;                 // re-zero for next graph replay
    }
    g_grpbase[NDEG]  = b;
    g_tilebase[NDEG] = tb;
    g_totaltiles = tb;
}

// ------------------------- kernel 3: build permutation ----------------------
__global__ void k_perm() {
    __shared__ int s_loc[6], s_base[6];
    int tid = threadIdx.x;
    if (tid < 6) s_loc[tid] = 0;
    __syncthreads();
    int g = blockIdx.x * 256 + tid;
    int d = g_deg[g];
    int l = atomicAdd(&s_loc[d], 1);
    __syncthreads();
    if (tid < 6) s_base[tid] = atomicAdd(&g_cnt[tid], s_loc[tid]);
    __syncthreads();
    g_perm[g_grpbase[d] + s_base[d] + l] = g;
}

// ------------------------- kernel 4: fused gather + tf32 mma GEMM -----------
#define LDT 132  // padded A row stride (floats): conflict-free fragment loads

static constexpr unsigned OFF_NODE = 0;                  // 128 ints
static constexpr unsigned OFF_BIAS = 512;                // 128 floats
static constexpr unsigned OFF_NBR  = 1024;               // 128*6 ints = 3072
static constexpr unsigned OFF_A    = 4096;               // 128*132*4 = 67584
static constexpr unsigned SMEM_TOTAL = OFF_A + 128 * LDT * 4;  // 71680 B

__global__ void __launch_bounds__(256, 2)
k_gemm(const float* __restrict__ atoms, const float* __restrict__ bias,
       float* __restrict__ out) {
    extern __shared__ __align__(16) unsigned char smem[];
    int tid = threadIdx.x, wid = tid >> 5, lane = tid & 31;
    int t = blockIdx.x;
    if (t >= g_totaltiles) return;   // uniform per CTA

    int d = 0;
    #pragma unroll
    for (int i = 0; i < NDEG - 1; i++)
        if (t >= g_tilebase[i + 1]) d = i + 1;
    int m0     = (t - g_tilebase[d]) << 7;
    int gstart = g_grpbase[d];
    int gcount = g_grpbase[d + 1] - g_grpbase[d];

    int*   sm_node = (int*)(smem + OFF_NODE);
    float* sm_bias = (float*)(smem + OFF_BIAS);
    int*   sm_nbr  = (int*)(smem + OFF_NBR);   // pre-resolved global row ids
    float* As      = (float*)(smem + OFF_A);   // [128][LDT]

    // --- phase 1: stage node ids + neighbor row ids + bias ---
    if (tid < 128) {
        sm_bias[tid] = bias[d * 128 + tid];
        int slot = m0 + tid;
        int node = (slot < gcount) ? g_perm[gstart + slot] : -1;
        sm_node[tid] = node;
        if (node >= 0) {
            int bb = node & ~(NNLOC - 1);
            const int2* nb2 = (const int2*)(g_nbr + node * 6);
            int2 e0 = nb2[0], e1 = nb2[1], e2 = nb2[2];
            sm_nbr[tid * 6 + 0] = bb + e0.x;
            sm_nbr[tid * 6 + 1] = bb + e0.y;
            sm_nbr[tid * 6 + 2] = bb + e1.x;
            sm_nbr[tid * 6 + 3] = bb + e1.y;
            sm_nbr[tid * 6 + 4] = bb + e2.x;
            sm_nbr[tid * 6 + 5] = bb + e2.y;
        }
    }
    __syncthreads();

    // --- phase 2: gather, 2 rows per iteration (high MLP), degree d uniform ---
    {
        int rbase = wid * 16;
        for (int i = 0; i < 16; i += 2) {
            int r0 = rbase + i, r1 = r0 + 1;
            int n0 = sm_node[r0], n1 = sm_node[r1];
            float4 acc0 = make_float4(0.f, 0.f, 0.f, 0.f);
            float4 acc1 = acc0;
            if (n0 >= 0) {
                acc0 = ((const float4*)(atoms + ((size_t)n0 << 7)))[lane];
                #pragma unroll
                for (int j = 0; j < 6; j++)
                    if (j < d) {
                        int gi = sm_nbr[r0 * 6 + j];
                        float4 v = ((const float4*)(atoms + ((size_t)gi << 7)))[lane];
                        acc0.x += v.x; acc0.y += v.y; acc0.z += v.z; acc0.w += v.w;
                    }
            }
            if (n1 >= 0) {
                acc1 = ((const float4*)(atoms + ((size_t)n1 << 7)))[lane];
                #pragma unroll
                for (int j = 0; j < 6; j++)
                    if (j < d) {
                        int gi = sm_nbr[r1 * 6 + j];
                        float4 v = ((const float4*)(atoms + ((size_t)gi << 7)))[lane];
                        acc1.x += v.x; acc1.y += v.y; acc1.z += v.z; acc1.w += v.w;
                    }
            }
            acc0.x = to_tf32(acc0.x); acc0.y = to_tf32(acc0.y);
            acc0.z = to_tf32(acc0.z); acc0.w = to_tf32(acc0.w);
            acc1.x = to_tf32(acc1.x); acc1.y = to_tf32(acc1.y);
            acc1.z = to_tf32(acc1.z); acc1.w = to_tf32(acc1.w);
            *(float4*)&As[r0 * LDT + lane * 4] = acc0;
            *(float4*)&As[r1 * LDT + lane * 4] = acc1;
        }
    }
    __syncthreads();

    // --- phase 3: mma.sync tf32, warp grid 4(M) x 2(N), each warp 32x64 ---
    int warp_m = wid & 3, warp_n = wid >> 2;
    int mb = warp_m * 32, nbase = warp_n * 64;
    int la = lane & 3, lg = lane >> 2;

    float acc[2][8][4];
    #pragma unroll
    for (int mt = 0; mt < 2; mt++)
        #pragma unroll
        for (int nt = 0; nt < 8; nt++)
            #pragma unroll
            for (int q = 0; q < 4; q++) acc[mt][nt][q] = 0.f;

    const uint32_t* Au = (const uint32_t*)As;
    // per-thread base into fragment-ordered W (float2 units)
    const float2* __restrict__ Wfd =
        g_Wf + ((size_t)d * 16 * 512) + (nbase + lg) * 4 + la;

    #pragma unroll
    for (int kk = 0; kk < 16; kk++) {
        int k0 = kk * 8;
        uint32_t a[2][4];
        #pragma unroll
        for (int mt = 0; mt < 2; mt++) {
            int r = mb + mt * 16 + lg;
            // PTX m16n8k8 tf32 A fragment: a0=(r,c) a1=(r+8,c) a2=(r,c+4) a3=(r+8,c+4)
            a[mt][0] = Au[r * LDT + k0 + la];
            a[mt][1] = Au[(r + 8) * LDT + k0 + la];
            a[mt][2] = Au[r * LDT + k0 + la + 4];
            a[mt][3] = Au[(r + 8) * LDT + k0 + la + 4];
        }
        const float2* wp = Wfd + kk * 512;
        #pragma unroll
        for (int nt = 0; nt < 8; nt++) {
            float2 bv = __ldg(wp + nt * 32);         // coalesced LDG.64, L1-resident
            uint32_t b0 = __float_as_uint(bv.x), b1 = __float_as_uint(bv.y);
            #pragma unroll
            for (int mt = 0; mt < 2; mt++)
                asm volatile(
                    "mma.sync.aligned.m16n8k8.row.col.f32.tf32.tf32.f32 "
                    "{%0,%1,%2,%3}, {%4,%5,%6,%7}, {%8,%9}, {%0,%1,%2,%3};"
                    : "+f"(acc[mt][nt][0]), "+f"(acc[mt][nt][1]),
                      "+f"(acc[mt][nt][2]), "+f"(acc[mt][nt][3])
                    : "r"(a[mt][0]), "r"(a[mt][1]), "r"(a[mt][2]), "r"(a[mt][3]),
                      "r"(b0), "r"(b1));
        }
    }
    __syncthreads();   // everyone done reading As before we overwrite it with C

    // --- stage C in smem (reuse A region) for coalesced output ---
    #pragma unroll
    for (int mt = 0; mt < 2; mt++) {
        int r = mb + mt * 16 + lg;
        #pragma unroll
        for (int nt = 0; nt < 8; nt++) {
            int c = nbase + nt * 8 + la * 2;
            *(float2*)&As[r * LDT + c]       = make_float2(acc[mt][nt][0], acc[mt][nt][1]);
            *(float2*)&As[(r + 8) * LDT + c] = make_float2(acc[mt][nt][2], acc[mt][nt][3]);
        }
    }
    __syncthreads();

    // --- bias + relu + coalesced scatter: warp w owns rows [16w, 16w+16) ---
    float4 bv = *(float4*)&sm_bias[lane * 4];
    #pragma unroll
    for (int i = 0; i < 16; i++) {
        int r = wid * 16 + i;
        int node = sm_node[r];
        if (node >= 0) {
            float4 v = *(float4*)&As[r * LDT + lane * 4];
            v.x = fmaxf(v.x + bv.x, 0.f);
            v.y = fmaxf(v.y + bv.y, 0.f);
            v.z = fmaxf(v.z + bv.z, 0.f);
            v.w = fmaxf(v.w + bv.w, 0.f);
            *(float4*)(out + ((size_t)node << 7) + lane * 4) = v;
        }
    }
}

// ------------------------- launch -------------------------------------------
extern "C" void kernel_launch(void* const* d_in, const int* in_sizes, int n_in,
                              void* d_out, int out_size) {
    const float* atoms = (const float*)d_in[0];
    const void*  edges = d_in[1];
    const float* W     = (const float*)d_in[2];
    const float* b     = (const float*)d_in[3];
    float* out = (float*)d_out;
    (void)in_sizes; (void)n_in; (void)out_size;

    cudaFuncSetAttribute(k_gemm, cudaFuncAttributeMaxDynamicSharedMemorySize, SMEM_TOTAL);

    k_prep_deg<<<NNODES / 256, 256>>>(W, edges);
    k_prefix<<<1, 1>>>();
    k_perm<<<NNODES / 256, 256>>>();
    k_gemm<<<MAXTILES, 256, SMEM_TOTAL>>>(atoms, b, out);
}

// round 10
// speedup vs baseline: 2.4323x; 1.3276x over previous
#include <cuda_runtime.h>
#include <cstdint>

// ---------------------------------------------------------------------------
// GraphConv: out[node] = relu(sum(self+neighbors) @ W[deg(node)] + b[deg(node)])
// Counting-sort nodes by degree, then per-128-row-tile tf32 mma.sync GEMM with
// fused high-MLP neighbor gather (A tile in SMEM) and fused bias+relu epilogue.
// R9: 512-thread CTAs (16 warps, 32x32 warp tiles, <=64 regs -> 2 CTAs/SM =
// 32 warps/SM), direct gmem epilogue (no C staging, no post-MMA barriers),
// 4-row-unrolled gather.
// NOTE: build targets plain sm_103 -> tcgen05/TMA unavailable; mma.sync it is.
// ---------------------------------------------------------------------------

#define NB      256
#define NNLOC   512
#define NNODES  (NB * NNLOC)      // 131072
#define DSLOTS  6
#define FIN     128
#define FOUT    128
#define NDEG    6
#define MAXTILES 1030             // ceil-sum bound is 1029

// ------------------------- device scratch (no allocs) ----------------------
__device__ int           g_nbr[NNODES * DSLOTS];
__device__ unsigned char g_deg[NNODES];
__device__ int           g_perm[NNODES];
__device__ int           g_hist[8];          // zero at load; k_prefix re-zeros
__device__ int           g_cnt[8];
__device__ int           g_grpbase[8];
__device__ int           g_tilebase[8];
__device__ int           g_totaltiles;
// W in B-fragment order: g_Wf[d][kk][n][la] = float2( Wt[n][kk*8+la], Wt[n][kk*8+la+4] )
// where Wt[n][k] = tf32(W[d][k][n]).  float2 index = ((d*16+kk)*128 + n)*4 + la
__device__ float2        g_Wf[NDEG * 16 * 128 * 4];

// ------------------------- helpers ------------------------------------------
__device__ __forceinline__ float to_tf32(float x) {
    uint32_t u = __float_as_uint(x), o;
    asm("cvt.rna.tf32.f32 %0, %1;" : "=r"(o) : "r"(u));
    return __uint_as_float(o);
}

// ------------------------- kernel 1: deg/hist + W fragment prep -------------
__global__ void k_prep_deg(const float* __restrict__ W, const void* __restrict__ edges) {
    __shared__ int sh[6];
    __shared__ int s_is64;
    int tid = threadIdx.x;
    if (tid < 6) sh[tid] = 0;
    if (tid == 0) {
        // sniff edges dtype: int64 -> every odd 32-bit word is 0 or -1
        const int* e32 = (const int*)edges;
        int is64 = 1;
        #pragma unroll 8
        for (int i = 0; i < 128; i++) {
            int hi = e32[2 * i + 1];
            if (hi != 0 && hi != -1) { is64 = 0; break; }
        }
        s_is64 = is64;
    }
    __syncthreads();

    // --- degree + neighbor extraction for node g ---
    int g = blockIdx.x * 256 + tid;
    int deg = 0;
    int nb[6];
    if (s_is64) {
        const long long* e = (const long long*)edges + (size_t)g * 6;
        #pragma unroll
        for (int j = 0; j < 6; j++) { long long v = e[j]; nb[j] = (int)v; deg += (v >= 0); }
    } else {
        const int* e = (const int*)edges + (size_t)g * 6;
        #pragma unroll
        for (int j = 0; j < 6; j++) { int v = e[j]; nb[j] = v; deg += (v >= 0); }
    }
    #pragma unroll
    for (int j = 0; j < 6; j++) g_nbr[g * 6 + j] = nb[j];
    g_deg[g] = (unsigned char)deg;
    atomicAdd(&sh[deg], 1);
    __syncthreads();
    if (tid < 6) atomicAdd(&g_hist[tid], sh[tid]);

    // --- W fragment prep: 49152 float2, blocks 0..191 ---
    int fid = blockIdx.x * 256 + tid;
    if (fid < NDEG * 16 * 128 * 4) {
        int d  = fid >> 13;            // / 8192
        int r  = fid & 8191;
        int kk = r >> 9;               // / 512
        int r2 = r & 511;
        int n  = r2 >> 2;
        int la = r2 & 3;
        int k0 = kk * 8;
        float lo = to_tf32(W[(d * 128 + (k0 + la)) * 128 + n]);
        float hi = to_tf32(W[(d * 128 + (k0 + la + 4)) * 128 + n]);
        g_Wf[fid] = make_float2(lo, hi);
    }
}

// ------------------------- kernel 2: prefix (self-cleaning) -----------------
__global__ void k_prefix() {
    int b = 0, tb = 0;
    for (int d = 0; d < NDEG; d++) {
        g_grpbase[d]  = b;
        g_tilebase[d] = tb;
        b  += g_hist[d];
        tb += (g_hist[d] + 127) >> 7;
        g_cnt[d]  = 0;
        g_hist[d] = 0;                 // re-zero for next graph replay
    }
    g_grpbase[NDEG]  = b;
    g_tilebase[NDEG] = tb;
    g_totaltiles = tb;
}

// ------------------------- kernel 3: build permutation ----------------------
__global__ void k_perm() {
    __shared__ int s_loc[6], s_base[6];
    int tid = threadIdx.x;
    if (tid < 6) s_loc[tid] = 0;
    __syncthreads();
    int g = blockIdx.x * 256 + tid;
    int d = g_deg[g];
    int l = atomicAdd(&s_loc[d], 1);
    __syncthreads();
    if (tid < 6) s_base[tid] = atomicAdd(&g_cnt[tid], s_loc[tid]);
    __syncthreads();
    g_perm[g_grpbase[d] + s_base[d] + l] = g;
}

// ------------------------- kernel 4: fused gather + tf32 mma GEMM -----------
#define LDT 132  // padded A row stride (floats): conflict-free fragment loads

static constexpr unsigned OFF_NODE = 0;                  // 128 ints
static constexpr unsigned OFF_BIAS = 512;                // 128 floats
static constexpr unsigned OFF_NBR  = 1024;               // 128*6 ints = 3072
static constexpr unsigned OFF_A    = 4096;               // 128*132*4 = 67584
static constexpr unsigned SMEM_TOTAL = OFF_A + 128 * LDT * 4;  // 71680 B

__global__ void __launch_bounds__(512, 2)
k_gemm(const float* __restrict__ atoms, const float* __restrict__ bias,
       float* __restrict__ out) {
    extern __shared__ __align__(16) unsigned char smem[];
    int tid = threadIdx.x, wid = tid >> 5, lane = tid & 31;
    int t = blockIdx.x;
    if (t >= g_totaltiles) return;   // uniform per CTA

    int d = 0;
    #pragma unroll
    for (int i = 0; i < NDEG - 1; i++)
        if (t >= g_tilebase[i + 1]) d = i + 1;
    int m0     = (t - g_tilebase[d]) << 7;
    int gstart = g_grpbase[d];
    int gcount = g_grpbase[d + 1] - g_grpbase[d];

    int*   sm_node = (int*)(smem + OFF_NODE);
    float* sm_bias = (float*)(smem + OFF_BIAS);
    int*   sm_nbr  = (int*)(smem + OFF_NBR);   // pre-resolved global row ids
    float* As      = (float*)(smem + OFF_A);   // [128][LDT]

    // --- phase 1: stage node ids + neighbor row ids + bias ---
    if (tid < 128) {
        sm_bias[tid] = bias[d * 128 + tid];
        int slot = m0 + tid;
        int node = (slot < gcount) ? g_perm[gstart + slot] : -1;
        sm_node[tid] = node;
        if (node >= 0) {
            int bb = node & ~(NNLOC - 1);
            const int2* nb2 = (const int2*)(g_nbr + node * 6);
            int2 e0 = nb2[0], e1 = nb2[1], e2 = nb2[2];
            sm_nbr[tid * 6 + 0] = bb + e0.x;
            sm_nbr[tid * 6 + 1] = bb + e0.y;
            sm_nbr[tid * 6 + 2] = bb + e1.x;
            sm_nbr[tid * 6 + 3] = bb + e1.y;
            sm_nbr[tid * 6 + 4] = bb + e2.x;
            sm_nbr[tid * 6 + 5] = bb + e2.y;
        }
    }
    __syncthreads();

    // --- phase 2: gather, warp owns 8 rows, 4-row unroll (high MLP) ---
    {
        int rbase = wid * 8;
        #pragma unroll
        for (int i = 0; i < 8; i += 4) {
            float4 a4[4];
            int    nd[4];
            #pragma unroll
            for (int u = 0; u < 4; u++) {
                int r = rbase + i + u;
                nd[u] = sm_node[r];
                a4[u] = make_float4(0.f, 0.f, 0.f, 0.f);
                if (nd[u] >= 0)
                    a4[u] = ((const float4*)(atoms + ((size_t)nd[u] << 7)))[lane];
            }
            #pragma unroll
            for (int j = 0; j < 6; j++)
                if (j < d) {
                    #pragma unroll
                    for (int u = 0; u < 4; u++)
                        if (nd[u] >= 0) {
                            int gi = sm_nbr[(rbase + i + u) * 6 + j];
                            float4 v = ((const float4*)(atoms + ((size_t)gi << 7)))[lane];
                            a4[u].x += v.x; a4[u].y += v.y;
                            a4[u].z += v.z; a4[u].w += v.w;
                        }
                }
            #pragma unroll
            for (int u = 0; u < 4; u++) {
                a4[u].x = to_tf32(a4[u].x); a4[u].y = to_tf32(a4[u].y);
                a4[u].z = to_tf32(a4[u].z); a4[u].w = to_tf32(a4[u].w);
                *(float4*)&As[(rbase + i + u) * LDT + lane * 4] = a4[u];
            }
        }
    }
    __syncthreads();

    // --- phase 3: mma.sync tf32, warp grid 4(M) x 4(N), each warp 32x32 ---
    int warp_m = wid & 3, warp_n = wid >> 2;
    int mb = warp_m * 32, nbase = warp_n * 32;
    int la = lane & 3, lg = lane >> 2;

    float acc[2][4][4];
    #pragma unroll
    for (int mt = 0; mt < 2; mt++)
        #pragma unroll
        for (int nt = 0; nt < 4; nt++)
            #pragma unroll
            for (int q = 0; q < 4; q++) acc[mt][nt][q] = 0.f;

    const uint32_t* Au = (const uint32_t*)As;
    // per-thread base into fragment-ordered W (float2 units)
    const float2* __restrict__ Wfd =
        g_Wf + ((size_t)d * 16 * 512) + (nbase + lg) * 4 + la;

    #pragma unroll
    for (int kk = 0; kk < 16; kk++) {
        int k0 = kk * 8;
        uint32_t a[2][4];
        #pragma unroll
        for (int mt = 0; mt < 2; mt++) {
            int r = mb + mt * 16 + lg;
            // PTX m16n8k8 tf32 A fragment: a0=(r,c) a1=(r+8,c) a2=(r,c+4) a3=(r+8,c+4)
            a[mt][0] = Au[r * LDT + k0 + la];
            a[mt][1] = Au[(r + 8) * LDT + k0 + la];
            a[mt][2] = Au[r * LDT + k0 + la + 4];
            a[mt][3] = Au[(r + 8) * LDT + k0 + la + 4];
        }
        const float2* wp = Wfd + kk * 512;
        #pragma unroll
        for (int nt = 0; nt < 4; nt++) {
            float2 bv = __ldg(wp + nt * 32);         // coalesced LDG.64, L1-resident
            uint32_t b0 = __float_as_uint(bv.x), b1 = __float_as_uint(bv.y);
            #pragma unroll
            for (int mt = 0; mt < 2; mt++)
                asm volatile(
                    "mma.sync.aligned.m16n8k8.row.col.f32.tf32.tf32.f32 "
                    "{%0,%1,%2,%3}, {%4,%5,%6,%7}, {%8,%9}, {%0,%1,%2,%3};"
                    : "+f"(acc[mt][nt][0]), "+f"(acc[mt][nt][1]),
                      "+f"(acc[mt][nt][2]), "+f"(acc[mt][nt][3])
                    : "r"(a[mt][0]), "r"(a[mt][1]), "r"(a[mt][2]), "r"(a[mt][3]),
                      "r"(b0), "r"(b1));
        }
    }

    // --- epilogue: direct gmem write, bias + relu (no barrier, no staging) ---
    // C fragment: c0,c1 at (row lg,   col la*2, la*2+1)
    //             c2,c3 at (row lg+8, col la*2, la*2+1)
    #pragma unroll
    for (int mt = 0; mt < 2; mt++) {
        int r  = mb + mt * 16 + lg;
        int n0 = sm_node[r];
        int n1 = sm_node[r + 8];
        #pragma unroll
        for (int nt = 0; nt < 4; nt++) {
            int c = nbase + nt * 8 + la * 2;
            float2 bv = *(float2*)&sm_bias[c];
            if (n0 >= 0) {
                float2 v = make_float2(fmaxf(acc[mt][nt][0] + bv.x, 0.f),
                                       fmaxf(acc[mt][nt][1] + bv.y, 0.f));
                *(float2*)(out + ((size_t)n0 << 7) + c) = v;
            }
            if (n1 >= 0) {
                float2 v = make_float2(fmaxf(acc[mt][nt][2] + bv.x, 0.f),
                                       fmaxf(acc[mt][nt][3] + bv.y, 0.f));
                *(float2*)(out + ((size_t)n1 << 7) + c) = v;
            }
        }
    }
}

// ------------------------- launch -------------------------------------------
extern "C" void kernel_launch(void* const* d_in, const int* in_sizes, int n_in,
                              void* d_out, int out_size) {
    const float* atoms = (const float*)d_in[0];
    const void*  edges = d_in[1];
    const float* W     = (const float*)d_in[2];
    const float* b     = (const float*)d_in[3];
    float* out = (float*)d_out;
    (void)in_sizes; (void)n_in; (void)out_size;

    cudaFuncSetAttribute(k_gemm, cudaFuncAttributeMaxDynamicSharedMemorySize, SMEM_TOTAL);

    k_prep_deg<<<NNODES / 256, 256>>>(W, edges);
    k_prefix<<<1, 1>>>();
    k_perm<<<NNODES / 256, 256>>>();
    k_gemm<<<MAXTILES, 512, SMEM_TOTAL>>>(atoms, b, out);
}

// round 13
// speedup vs baseline: 2.5481x; 1.0476x over previous
#include <cuda_runtime.h>
#include <cstdint>

// ---------------------------------------------------------------------------
// GraphConv: out[node] = relu(sum(self+neighbors) @ W[deg(node)] + b[deg(node)])
// Counting-sort nodes by degree, then per-64-row-tile tf32 mma.sync GEMM with
// fused high-MLP neighbor gather (A tile in SMEM) and fused bias+relu epilogue.
// R11: 64-row tiles, 256-thread CTAs, 4 CTAs/SM (4 independent barrier domains
// -> phase overlap feeds L1/LSU continuously), direct gmem epilogue.
// NOTE: build targets plain sm_103 -> tcgen05/TMA unavailable; mma.sync it is.
// ---------------------------------------------------------------------------

#define NB      256
#define NNLOC   512
#define NNODES  (NB * NNLOC)      // 131072
#define DSLOTS  6
#define FIN     128
#define FOUT    128
#define NDEG    6
#define NTILE   64
#define MAXTILES 2054             // 131072/64 + 6

// ------------------------- device scratch (no allocs) ----------------------
__device__ int           g_nbr[NNODES * DSLOTS];
__device__ unsigned char g_deg[NNODES];
__device__ int           g_perm[NNODES];
__device__ int           g_hist[8];          // zero at load; k_prefix re-zeros
__device__ int           g_cnt[8];
__device__ int           g_grpbase[8];
__device__ int           g_tilebase[8];
__device__ int           g_totaltiles;
// W in B-fragment order: g_Wf[d][kk][n][la] = float2( Wt[n][kk*8+la], Wt[n][kk*8+la+4] )
// where Wt[n][k] = tf32(W[d][k][n]).  float2 index = ((d*16+kk)*128 + n)*4 + la
__device__ float2        g_Wf[NDEG * 16 * 128 * 4];

// ------------------------- helpers ------------------------------------------
__device__ __forceinline__ float to_tf32(float x) {
    uint32_t u = __float_as_uint(x), o;
    asm("cvt.rna.tf32.f32 %0, %1;" : "=r"(o) : "r"(u));
    return __uint_as_float(o);
}

// ------------------------- kernel 1: deg/hist + W fragment prep -------------
__global__ void k_prep_deg(const float* __restrict__ W, const void* __restrict__ edges) {
    __shared__ int sh[6];
    __shared__ int s_is64;
    int tid = threadIdx.x;
    if (tid < 6) sh[tid] = 0;
    if (tid == 0) {
        // sniff edges dtype: int64 -> every odd 32-bit word is 0 or -1
        const int* e32 = (const int*)edges;
        int is64 = 1;
        #pragma unroll 8
        for (int i = 0; i < 128; i++) {
            int hi = e32[2 * i + 1];
            if (hi != 0 && hi != -1) { is64 = 0; break; }
        }
        s_is64 = is64;
    }
    __syncthreads();

    // --- degree + neighbor extraction for node g ---
    int g = blockIdx.x * 256 + tid;
    int deg = 0;
    int nb[6];
    if (s_is64) {
        const long long* e = (const long long*)edges + (size_t)g * 6;
        #pragma unroll
        for (int j = 0; j < 6; j++) { long long v = e[j]; nb[j] = (int)v; deg += (v >= 0); }
    } else {
        const int* e = (const int*)edges + (size_t)g * 6;
        #pragma unroll
        for (int j = 0; j < 6; j++) { int v = e[j]; nb[j] = v; deg += (v >= 0); }
    }
    #pragma unroll
    for (int j = 0; j < 6; j++) g_nbr[g * 6 + j] = nb[j];
    g_deg[g] = (unsigned char)deg;
    atomicAdd(&sh[deg], 1);
    __syncthreads();
    if (tid < 6) atomicAdd(&g_hist[tid], sh[tid]);

    // --- W fragment prep: 49152 float2, blocks 0..191 ---
    int fid = blockIdx.x * 256 + tid;
    if (fid < NDEG * 16 * 128 * 4) {
        int d  = fid >> 13;            // / 8192
        int r  = fid & 8191;
        int kk = r >> 9;               // / 512
        int r2 = r & 511;
        int n  = r2 >> 2;
        int la = r2 & 3;
        int k0 = kk * 8;
        float lo = to_tf32(W[(d * 128 + (k0 + la)) * 128 + n]);
        float hi = to_tf32(W[(d * 128 + (k0 + la + 4)) * 128 + n]);
        g_Wf[fid] = make_float2(lo, hi);
    }
}

// ------------------------- kernel 2: prefix (self-cleaning) -----------------
__global__ void k_prefix() {
    int b = 0, tb = 0;
    for (int d = 0; d < NDEG; d++) {
        g_grpbase[d]  = b;
        g_tilebase[d] = tb;
        b  += g_hist[d];
        tb += (g_hist[d] + NTILE - 1) / NTILE;
        g_cnt[d]  = 0;
        g_hist[d] = 0;                 // re-zero for next graph replay
    }
    g_grpbase[NDEG]  = b;
    g_tilebase[NDEG] = tb;
    g_totaltiles = tb;
}

// ------------------------- kernel 3: build permutation ----------------------
__global__ void k_perm() {
    __shared__ int s_loc[6], s_base[6];
    int tid = threadIdx.x;
    if (tid < 6) s_loc[tid] = 0;
    __syncthreads();
    int g = blockIdx.x * 256 + tid;
    int d = g_deg[g];
    int l = atomicAdd(&s_loc[d], 1);
    __syncthreads();
    if (tid < 6) s_base[tid] = atomicAdd(&g_cnt[tid], s_loc[tid]);
    __syncthreads();
    g_perm[g_grpbase[d] + s_base[d] + l] = g;
}

// ------------------------- kernel 4: fused gather + tf32 mma GEMM -----------
#define LDT 132  // padded A row stride (floats): conflict-free fragment loads

static constexpr unsigned OFF_NODE = 0;                  // 64 ints
static constexpr unsigned OFF_BIAS = 256;                // 128 floats -> [256,768)
static constexpr unsigned OFF_NBR  = 768;                // 64*6 ints = 1536 -> [768,2304)
static constexpr unsigned OFF_A    = 2304;               // 64*132*4 = 33792
static constexpr unsigned SMEM_TOTAL = OFF_A + NTILE * LDT * 4;  // 36096 B

__global__ void __launch_bounds__(256, 4)
k_gemm(const float* __restrict__ atoms, const float* __restrict__ bias,
       float* __restrict__ out) {
    extern __shared__ __align__(16) unsigned char smem[];
    int tid = threadIdx.x, wid = tid >> 5, lane = tid & 31;
    int t = blockIdx.x;
    if (t >= g_totaltiles) return;   // uniform per CTA

    int d = 0;
    #pragma unroll
    for (int i = 0; i < NDEG - 1; i++)
        if (t >= g_tilebase[i + 1]) d = i + 1;
    int m0     = (t - g_tilebase[d]) * NTILE;
    int gstart = g_grpbase[d];
    int gcount = g_grpbase[d + 1] - g_grpbase[d];

    int*   sm_node = (int*)(smem + OFF_NODE);
    float* sm_bias = (float*)(smem + OFF_BIAS);
    int*   sm_nbr  = (int*)(smem + OFF_NBR);   // pre-resolved global row ids
    float* As      = (float*)(smem + OFF_A);   // [64][LDT]

    // --- phase 1: stage node ids + neighbor row ids + bias ---
    if (tid < 128) sm_bias[tid] = bias[d * 128 + tid];
    if (tid < NTILE) {
        int slot = m0 + tid;
        int node = (slot < gcount) ? g_perm[gstart + slot] : -1;
        sm_node[tid] = node;
        if (node >= 0) {
            int bb = node & ~(NNLOC - 1);
            const int2* nb2 = (const int2*)(g_nbr + node * 6);
            int2 e0 = nb2[0], e1 = nb2[1], e2 = nb2[2];
            sm_nbr[tid * 6 + 0] = bb + e0.x;
            sm_nbr[tid * 6 + 1] = bb + e0.y;
            sm_nbr[tid * 6 + 2] = bb + e1.x;
            sm_nbr[tid * 6 + 3] = bb + e1.y;
            sm_nbr[tid * 6 + 4] = bb + e2.x;
            sm_nbr[tid * 6 + 5] = bb + e2.y;
        }
    }
    __syncthreads();

    // --- phase 2: gather, warp owns 8 rows, 4-row unroll (high MLP) ---
    {
        int rbase = wid * 8;
        #pragma unroll
        for (int i = 0; i < 8; i += 4) {
            float4 a4[4];
            int    nd[4];
            #pragma unroll
            for (int u = 0; u < 4; u++) {
                int r = rbase + i + u;
                nd[u] = sm_node[r];
                a4[u] = make_float4(0.f, 0.f, 0.f, 0.f);
                if (nd[u] >= 0)
                    a4[u] = ((const float4*)(atoms + ((size_t)nd[u] << 7)))[lane];
            }
            #pragma unroll
            for (int j = 0; j < 6; j++)
                if (j < d) {
                    #pragma unroll
                    for (int u = 0; u < 4; u++)
                        if (nd[u] >= 0) {
                            int gi = sm_nbr[(rbase + i + u) * 6 + j];
                            float4 v = ((const float4*)(atoms + ((size_t)gi << 7)))[lane];
                            a4[u].x += v.x; a4[u].y += v.y;
                            a4[u].z += v.z; a4[u].w += v.w;
                        }
                }
            #pragma unroll
            for (int u = 0; u < 4; u++) {
                a4[u].x = to_tf32(a4[u].x); a4[u].y = to_tf32(a4[u].y);
                a4[u].z = to_tf32(a4[u].z); a4[u].w = to_tf32(a4[u].w);
                *(float4*)&As[(rbase + i + u) * LDT + lane * 4] = a4[u];
            }
        }
    }
    __syncthreads();

    // --- phase 3: mma.sync tf32, warp grid 2(M) x 4(N), each warp 32x32 ---
    int warp_m = wid & 1, warp_n = wid >> 1;
    int mb = warp_m * 32, nbase = warp_n * 32;
    int la = lane & 3, lg = lane >> 2;

    float acc[2][4][4];
    #pragma unroll
    for (int mt = 0; mt < 2; mt++)
        #pragma unroll
        for (int nt = 0; nt < 4; nt++)
            #pragma unroll
            for (int q = 0; q < 4; q++) acc[mt][nt][q] = 0.f;

    const uint32_t* Au = (const uint32_t*)As;
    // per-thread base into fragment-ordered W (float2 units)
    const float2* __restrict__ Wfd =
        g_Wf + ((size_t)d * 16 * 512) + (nbase + lg) * 4 + la;

    #pragma unroll
    for (int kk = 0; kk < 16; kk++) {
        int k0 = kk * 8;
        uint32_t a[2][4];
        #pragma unroll
        for (int mt = 0; mt < 2; mt++) {
            int r = mb + mt * 16 + lg;
            // PTX m16n8k8 tf32 A fragment: a0=(r,c) a1=(r+8,c) a2=(r,c+4) a3=(r+8,c+4)
            a[mt][0] = Au[r * LDT + k0 + la];
            a[mt][1] = Au[(r + 8) * LDT + k0 + la];
            a[mt][2] = Au[r * LDT + k0 + la + 4];
            a[mt][3] = Au[(r + 8) * LDT + k0 + la + 4];
        }
        const float2* wp = Wfd + kk * 512;
        #pragma unroll
        for (int nt = 0; nt < 4; nt++) {
            float2 bv = __ldg(wp + nt * 32);         // coalesced LDG.64, L1-resident
            uint32_t b0 = __float_as_uint(bv.x), b1 = __float_as_uint(bv.y);
            #pragma unroll
            for (int mt = 0; mt < 2; mt++)
                asm volatile(
                    "mma.sync.aligned.m16n8k8.row.col.f32.tf32.tf32.f32 "
                    "{%0,%1,%2,%3}, {%4,%5,%6,%7}, {%8,%9}, {%0,%1,%2,%3};"
                    : "+f"(acc[mt][nt][0]), "+f"(acc[mt][nt][1]),
                      "+f"(acc[mt][nt][2]), "+f"(acc[mt][nt][3])
                    : "r"(a[mt][0]), "r"(a[mt][1]), "r"(a[mt][2]), "r"(a[mt][3]),
                      "r"(b0), "r"(b1));
        }
    }

    // --- epilogue: direct gmem write, bias + relu (no barrier, no staging) ---
    // C fragment: c0,c1 at (row lg,   col la*2, la*2+1)
    //             c2,c3 at (row lg+8, col la*2, la*2+1)
    #pragma unroll
    for (int mt = 0; mt < 2; mt++) {
        int r  = mb + mt * 16 + lg;
        int n0 = sm_node[r];
        int n1 = sm_node[r + 8];
        #pragma unroll
        for (int nt = 0; nt < 4; nt++) {
            int c = nbase + nt * 8 + la * 2;
            float2 bv = *(float2*)&sm_bias[c];
            if (n0 >= 0) {
                float2 v = make_float2(fmaxf(acc[mt][nt][0] + bv.x, 0.f),
                                       fmaxf(acc[mt][nt][1] + bv.y, 0.f));
                *(float2*)(out + ((size_t)n0 << 7) + c) = v;
            }
            if (n1 >= 0) {
                float2 v = make_float2(fmaxf(acc[mt][nt][2] + bv.x, 0.f),
                                       fmaxf(acc[mt][nt][3] + bv.y, 0.f));
                *(float2*)(out + ((size_t)n1 << 7) + c) = v;
            }
        }
    }
}

// ------------------------- launch -------------------------------------------
extern "C" void kernel_launch(void* const* d_in, const int* in_sizes, int n_in,
                              void* d_out, int out_size) {
    const float* atoms = (const float*)d_in[0];
    const void*  edges = d_in[1];
    const float* W     = (const float*)d_in[2];
    const float* b     = (const float*)d_in[3];
    float* out = (float*)d_out;
    (void)in_sizes; (void)n_in; (void)out_size;

    cudaFuncSetAttribute(k_gemm, cudaFuncAttributeMaxDynamicSharedMemorySize, SMEM_TOTAL);

    k_prep_deg<<<NNODES / 256, 256>>>(W, edges);
    k_prefix<<<1, 1>>>();
    k_perm<<<NNODES / 256, 256>>>();
    k_gemm<<<MAXTILES, 256, SMEM_TOTAL>>>(atoms, b, out);
}